// round 1
// baseline (speedup 1.0000x reference)
#include <cuda_runtime.h>

// Problem constants
#define NJ   24      // volumes
#define NP   32768   // points per volume
#define NF   42      // line features
#define NR   16      // feature resolution
#define DIN  126     // F*3 = MLP in/out dim
#define HID  32      // hidden
#define NIND 18      // individual (copied) channels
#define NOUTC 144    // output channels per point

// Shared memory carve (in floats). All float4-sensitive regions 16B aligned.
#define OFF_W1   0                       // [126][32] row-major        (4032)
#define OFF_HS   4032                    // 4 warps * 32 pts * 36 pad  (4608)
#define OFF_FEAT (4032 + 4608)           // [f][r][c] = 42*16*3        (2016)
#define OFF_B1   (OFF_FEAT + 2016)       // 32
#define OFF_B2   (OFF_B1 + 32)           // 126
#define OFF_W2T  (OFF_B2 + 128)          // [k][o] pad 33 -> 126*33    (4158), padded start
#define SMEM_FLOATS (OFF_W2T + 126 * 33)

extern "C" __global__ void __launch_bounds__(128)
v3d_fused_kernel(const float* __restrict__ pts,
                 const float* __restrict__ feature,
                 const float* __restrict__ ind,
                 const float* __restrict__ w1,
                 const float* __restrict__ b1,
                 const float* __restrict__ w2,
                 const float* __restrict__ b2,
                 float* __restrict__ out)
{
    extern __shared__ float sm[];
    float* w1s   = sm + OFF_W1;
    float* hs    = sm + OFF_HS;
    float* sfeat = sm + OFF_FEAT;
    float* b1s   = sm + OFF_B1;
    float* b2s   = sm + OFF_B2;
    float* w2t   = sm + OFF_W2T;

    const int j    = blockIdx.y;
    const int tid  = threadIdx.x;
    const int lane = tid & 31;
    const int warp = tid >> 5;

    // ---- Stage per-volume constants into shared ----
    {
        const float* w1g = w1 + j * (DIN * HID);
        for (int idx = tid; idx < DIN * HID; idx += 128) w1s[idx] = w1g[idx];
        const float* w2g = w2 + j * (HID * DIN);
        for (int idx = tid; idx < HID * DIN; idx += 128) {
            int o = idx / DIN;
            int k = idx - o * DIN;
            w2t[k * 33 + o] = w2g[idx];          // transpose: [k][o], pad 33
        }
        const float* fg = feature + j * (NF * NR * 3);
        for (int idx = tid; idx < NF * NR * 3; idx += 128) sfeat[idx] = fg[idx];
        if (tid < HID) b1s[tid] = b1[j * HID + tid];
        if (tid < DIN) b2s[tid] = b2[j * DIN + tid];
    }
    __syncthreads();

    // 2 tiles of 128 points per block (grid.x = 128)
    #pragma unroll 1
    for (int t = 0; t < 2; ++t) {
        const int p0 = (blockIdx.x * 2 + t) * 128;

        // ================= Phase 1: per-thread point -> h[32] =================
        const int p = p0 + tid;
        const float* ptp = pts + ((size_t)j * NP + p) * 3;

        int   rbase[3];
        float wc[3];
        #pragma unroll
        for (int c = 0; c < 3; ++c) {
            float x = fminf(fmaxf(fmaf(ptp[c], 7.5f, 7.5f), 0.0f), 15.0f);
            int x0 = (int)x;               // floor (x >= 0)
            if (x0 > NR - 2) x0 = NR - 2;
            wc[c]   = x - (float)x0;
            rbase[c] = x0 * 3 + c;
        }

        float h[HID];
        #pragma unroll
        for (int o = 0; o < HID; ++o) h[o] = b1s[o];

        #pragma unroll 3
        for (int f = 0; f < NF; ++f) {
            const float* frow = sfeat + f * (NR * 3);
            #pragma unroll
            for (int c = 0; c < 3; ++c) {
                float g0 = frow[rbase[c]];
                float g1 = frow[rbase[c] + 3];
                float v  = fmaf(wc[c], g1 - g0, g0);
                const float4* wrow = (const float4*)(w1s + (f * 3 + c) * HID);
                #pragma unroll
                for (int oq = 0; oq < 8; ++oq) {
                    float4 wv = wrow[oq];
                    h[4 * oq + 0] = fmaf(v, wv.x, h[4 * oq + 0]);
                    h[4 * oq + 1] = fmaf(v, wv.y, h[4 * oq + 1]);
                    h[4 * oq + 2] = fmaf(v, wv.z, h[4 * oq + 2]);
                    h[4 * oq + 3] = fmaf(v, wv.w, h[4 * oq + 3]);
                }
            }
        }

        // ReLU + warp-local transpose into shared (stride 36: conflict-free STS.128)
        {
            float4* myh4 = (float4*)(hs + (warp * 32 + lane) * 36);
            #pragma unroll
            for (int oq = 0; oq < 8; ++oq) {
                float4 hv;
                hv.x = fmaxf(h[4 * oq + 0], 0.0f);
                hv.y = fmaxf(h[4 * oq + 1], 0.0f);
                hv.z = fmaxf(h[4 * oq + 2], 0.0f);
                hv.w = fmaxf(h[4 * oq + 3], 0.0f);
                myh4[oq] = hv;
            }
        }
        __syncwarp();

        // ================= Phase 2: warp handles its 32 points, lane = out channel =========
        const int pw0 = p0 + warp * 32;
        float*       outg = out + ((size_t)j * NP + pw0) * NOUTC;
        const float* indg = ind + ((size_t)j * NP + pw0) * NIND;

        // Fused ind_feature copy (coalesced reads)
        for (int idx = lane; idx < 32 * NIND; idx += 32) {
            int pp = idx / NIND;
            int c  = idx - pp * NIND;
            outg[pp * NOUTC + c] = indg[idx];
        }

        const float* whs = hs + warp * (32 * 36);
        #pragma unroll 1
        for (int kk = 0; kk < 4; ++kk) {
            int  k     = kk * 32 + lane;
            bool valid = (k < DIN);
            int  ksafe = valid ? k : 0;

            float wreg[HID];
            #pragma unroll
            for (int o = 0; o < HID; ++o) wreg[o] = w2t[ksafe * 33 + o];
            float bias = b2s[ksafe];

            #pragma unroll 4
            for (int pp = 0; pp < 32; ++pp) {
                const float4* hp = (const float4*)(whs + pp * 36);
                float acc = bias;
                #pragma unroll
                for (int oq = 0; oq < 8; ++oq) {
                    float4 hv = hp[oq];
                    acc = fmaf(hv.x, wreg[4 * oq + 0], acc);
                    acc = fmaf(hv.y, wreg[4 * oq + 1], acc);
                    acc = fmaf(hv.z, wreg[4 * oq + 2], acc);
                    acc = fmaf(hv.w, wreg[4 * oq + 3], acc);
                }
                if (valid) outg[pp * NOUTC + NIND + k] = acc;   // coalesced across lanes
            }
        }
        __syncwarp();   // protect hs before next tile's phase-1 stores
    }
}

extern "C" void kernel_launch(void* const* d_in, const int* in_sizes, int n_in,
                              void* d_out, int out_size)
{
    const float* pts     = (const float*)d_in[0];
    const float* feature = (const float*)d_in[1];
    const float* ind     = (const float*)d_in[2];
    const float* w1      = (const float*)d_in[3];
    const float* b1      = (const float*)d_in[4];
    const float* w2      = (const float*)d_in[5];
    const float* b2      = (const float*)d_in[6];
    float*       out     = (float*)d_out;

    const size_t smem = SMEM_FLOATS * sizeof(float);   // ~58.5 KB
    cudaFuncSetAttribute(v3d_fused_kernel,
                         cudaFuncAttributeMaxDynamicSharedMemorySize, (int)smem);

    dim3 grid(128, NJ);   // 128 blocks/volume * 2 tiles = 32768 pts
    dim3 block(128);
    v3d_fused_kernel<<<grid, block, smem>>>(pts, feature, ind, w1, b1, w2, b2, out);
}